// round 13
// baseline (speedup 1.0000x reference)
#include <cuda_runtime.h>
#include <cuda_fp16.h>

#define Bx     2
#define Hx     512
#define Wx     1024
#define HWx    (Hx * Wx)          // 524288
#define NSEG   16
#define NBINS  32768
#define BIN_SCALE 16384.0f
#define MINPIX 128.0f
#define BPB    256                // blocks per batch for big passes

// ---- globals ----
__device__ __align__(16) unsigned long long g_hist[NSEG * NBINS];  // 4MB; low=neg, high=pos
__device__ __align__(16) float g_acc[NSEG * 6];        // cnt, Se0, Se1, Ss0, Ss1, Q
__device__ __align__(16) float g_lov[NSEG];
__device__ __align__(16) float g_params[NSEG * 4];     // c0 c1 sx0 sx1
// per-block partials (fully overwritten each run; no zeroing needed)
__device__ __align__(16) float g_acc_part[96 * 256];   // [q][blk] q=(b*8+n)*6+j
__device__ __align__(16) float g_bg_part[2 * 256];     // [b][blk]
__device__ __align__(16) float g_fg_part[NSEG * 256];  // [seg][blk]
// scratch
__device__ __align__(16) __half g_seeds[Bx * 8 * HWx];       // [b][c][hw]
__device__ __align__(16) unsigned g_mbits[Bx * HWx / 4];     // byte j: bit n = mask n

__device__ const float FGW[8] = {10.0f, 10.0f, 10.0f, 40.0f, 80.0f, 100.0f, 60.0f, 20.0f};

__device__ __forceinline__ float wred(float v) {
    v += __shfl_down_sync(0xffffffffu, v, 16);
    v += __shfl_down_sync(0xffffffffu, v, 8);
    v += __shfl_down_sync(0xffffffffu, v, 4);
    v += __shfl_down_sync(0xffffffffu, v, 2);
    v += __shfl_down_sync(0xffffffffu, v, 1);
    return v;
}

__device__ __forceinline__ float tanh_approx(float x) {
    float r;
    asm("tanh.approx.f32 %0, %1;" : "=f"(r) : "f"(x));
    return r;
}
__device__ __forceinline__ __half2 sigmoid2_h(float a, float b) {
    __half2 x = __floats2half2_rn(0.5f * a, 0.5f * b);
    __half2 t;
    asm("tanh.approx.f16x2 %0, %1;" : "=r"(*(unsigned*)&t) : "r"(*(unsigned*)&x));
    const __half2 half2_half = __floats2half2_rn(0.5f, 0.5f);
    return __hfma2(t, half2_half, half2_half);
}

// ---------------------------------------------------------------- k_seed: ch4-11 + bbox, zeroes hist (launch 0)
__global__ void __launch_bounds__(256, 4) k_seed(const float* __restrict__ pred,
                                                 const int* __restrict__ bbox) {
    int b = blockIdx.x / BPB;
    int blk = blockIdx.x % BPB;
    const float* pb = pred + (size_t)b * 12 * HWx;
    const int* bbb = bbox + (size_t)b * 9 * HWx;
    __half* sdo = g_seeds + (size_t)b * 8 * HWx;

    // zero the histogram (4MB = 262144 float4s over 512 blocks x 256 threads x 2)
    {
        float4* hz = reinterpret_cast<float4*>(g_hist);
        int base = blockIdx.x * 512 + threadIdx.x;
        hz[base] = make_float4(0.f, 0.f, 0.f, 0.f);
        hz[base + 256] = make_float4(0.f, 0.f, 0.f, 0.f);
    }

    float bg = 0.f;
    for (int g = blk * 256 + threadIdx.x; g < HWx / 4; g += BPB * 256) {
        int hw = g * 4;
#pragma unroll
        for (int c = 0; c < 8; c++) {
            float4 sv = *(const float4*)(pb + (size_t)(4 + c) * HWx + hw);
            int4 bv = *(const int4*)(bbb + (size_t)(1 + c) * HWx + hw);
            __half2 s01 = sigmoid2_h(sv.x, sv.y);
            __half2 s23 = sigmoid2_h(sv.z, sv.w);
            float2 f01 = __half22float2(s01);
            float2 f23 = __half22float2(s23);
            if (bv.x == 0) bg = fmaf(f01.x, f01.x, bg);
            if (bv.y == 0) bg = fmaf(f01.y, f01.y, bg);
            if (bv.z == 0) bg = fmaf(f23.x, f23.x, bg);
            if (bv.w == 0) bg = fmaf(f23.y, f23.y, bg);
            uint2 pk;
            pk.x = *reinterpret_cast<unsigned*>(&s01);
            pk.y = *reinterpret_cast<unsigned*>(&s23);
            *(uint2*)(sdo + (size_t)c * HWx + hw) = pk;
        }
    }
    __shared__ float s_bg[8];
    int warp = threadIdx.x >> 5, lane = threadIdx.x & 31;
    bg = wred(bg);
    if (lane == 0) s_bg[warp] = bg;
    __syncthreads();
    if (threadIdx.x == 0) {
        float s = 0.f;
#pragma unroll
        for (int wv = 0; wv < 8; wv++) s += s_bg[wv];
        g_bg_part[b * 256 + blk] = s;
    }
}

// ---------------------------------------------------------------- k_maskaccum: masks + ch0-3 -> mbits + sums (launch 1)
__global__ void __launch_bounds__(256) k_maskaccum(const float* __restrict__ pred,
                                                   const int* __restrict__ masks) {
    int b = blockIdx.x / BPB;
    int blk = blockIdx.x % BPB;
    const float* pb = pred + (size_t)b * 12 * HWx;
    const int* mb  = masks + (size_t)b * 8 * HWx;
    unsigned* mbo = g_mbits + (size_t)b * HWx / 4;

    float acc[8][5];   // Se0, Se1, Ss0, Ss1, Q
    int cnt[8];
#pragma unroll
    for (int n = 0; n < 8; n++) {
        cnt[n] = 0;
#pragma unroll
        for (int j = 0; j < 5; j++) acc[n][j] = 0.f;
    }

    for (int g = blk * 256 + threadIdx.x; g < HWx / 4; g += BPB * 256) {
        int hw = g * 4;
        int w = hw & (Wx - 1);
        int h = hw >> 10;
        float ybase = (float)h * (1.0f / 1023.0f);

        unsigned bits = 0;
#pragma unroll
        for (int n = 0; n < 8; n++) {
            int4 mv = *(const int4*)(mb + (size_t)n * HWx + hw);
            if (mv.x > 0) bits |= (1u << (n + 0));
            if (mv.y > 0) bits |= (1u << (n + 8));
            if (mv.z > 0) bits |= (1u << (n + 16));
            if (mv.w > 0) bits |= (1u << (n + 24));
        }
        mbo[g] = bits;

        float4 p0 = *(const float4*)(pb + hw);
        float4 p1 = *(const float4*)(pb + HWx + hw);
        float4 s0v = *(const float4*)(pb + 2 * HWx + hw);
        float4 s1v = *(const float4*)(pb + 3 * HWx + hw);

        float e0[4], e1[4];
        e0[0] = tanh_approx(p0.x) + (float)(w + 0) * (2.0f / 2047.0f);
        e0[1] = tanh_approx(p0.y) + (float)(w + 1) * (2.0f / 2047.0f);
        e0[2] = tanh_approx(p0.z) + (float)(w + 2) * (2.0f / 2047.0f);
        e0[3] = tanh_approx(p0.w) + (float)(w + 3) * (2.0f / 2047.0f);
        e1[0] = tanh_approx(p1.x) + ybase;
        e1[1] = tanh_approx(p1.y) + ybase;
        e1[2] = tanh_approx(p1.z) + ybase;
        e1[3] = tanh_approx(p1.w) + ybase;
        float sg0[4] = {s0v.x, s0v.y, s0v.z, s0v.w};
        float sg1[4] = {s1v.x, s1v.y, s1v.z, s1v.w};
        float q4[4];
#pragma unroll
        for (int j = 0; j < 4; j++) q4[j] = fmaf(sg0[j], sg0[j], sg1[j] * sg1[j]);

#pragma unroll
        for (int n = 0; n < 8; n++) {
            cnt[n] += __popc(bits & (0x01010101u << n));
#pragma unroll
            for (int j = 0; j < 4; j++) {
                if ((bits >> (n + j * 8)) & 1u) {
                    acc[n][0] += e0[j];
                    acc[n][1] += e1[j];
                    acc[n][2] += sg0[j];
                    acc[n][3] += sg1[j];
                    acc[n][4] += q4[j];
                }
            }
        }
    }

    __shared__ float s_red[48][8];
    int warp = threadIdx.x >> 5, lane = threadIdx.x & 31;
#pragma unroll
    for (int n = 0; n < 8; n++) {
        float v;
        v = wred((float)cnt[n]); if (lane == 0) s_red[n * 6 + 0][warp] = v;
#pragma unroll
        for (int j = 0; j < 5; j++) {
            v = wred(acc[n][j]);
            if (lane == 0) s_red[n * 6 + 1 + j][warp] = v;
        }
    }
    __syncthreads();
    if (threadIdx.x < 48) {
        float s = 0.f;
#pragma unroll
        for (int wv = 0; wv < 8; wv++) s += s_red[threadIdx.x][wv];
        int q = (b * 8 + (threadIdx.x / 6)) * 6 + (threadIdx.x % 6);
        g_acc_part[q * 256 + blk] = s;
    }
}

// ---------------------------------------------------------------- k_params: reduce partials (launch 2)
__global__ void __launch_bounds__(1024) k_params() {
    __shared__ float sq[96];
    int warp = threadIdx.x >> 5, lane = threadIdx.x & 31;
    for (int q = warp; q < 96; q += 32) {
        float v = 0.f;
#pragma unroll
        for (int i = 0; i < 8; i++) v += g_acc_part[q * 256 + lane + i * 32];
        v = wred(v);
        if (lane == 0) sq[q] = v;
    }
    __syncthreads();
    int tid = threadIdx.x;
    if (tid < NSEG) {
        float cnt = sq[tid * 6 + 0];
        float cs = fmaxf(cnt, 1.f);
        float inv = 1.f / cs;
#pragma unroll
        for (int j = 0; j < 6; j++) g_acc[tid * 6 + j] = sq[tid * 6 + j];
        g_params[tid * 4 + 0] = sq[tid * 6 + 1] * inv;
        g_params[tid * 4 + 1] = sq[tid * 6 + 2] * inv;
        g_params[tid * 4 + 2] = expf(sq[tid * 6 + 3] * inv * 10.f);
        g_params[tid * 4 + 3] = expf(sq[tid * 6 + 4] * inv * 10.f);
    }
}

// ---------------------------------------------------------------- pass3: dist, hist, seed_fg (launch 3 <- profiled)
__global__ void __launch_bounds__(256, 2) k_pass3(const float* __restrict__ pred,
                                                  const int* __restrict__ cls_ids) {
    int b = blockIdx.x / BPB;
    int blk = blockIdx.x % BPB;

    __shared__ float sp[8][4];
    __shared__ int sch[8];
    if (threadIdx.x < 32) {
        int n = threadIdx.x / 4, k = threadIdx.x % 4;
        sp[n][k] = g_params[(b * 8 + n) * 4 + k];
    }
    if (threadIdx.x < 8) sch[threadIdx.x] = cls_ids[b * 8 + threadIdx.x];
    __syncthreads();

    float c0[8], c1[8], sx0[8], sx1[8];
    unsigned soff[8];
    const __half* sbase = g_seeds + (size_t)b * 8 * HWx;
#pragma unroll
    for (int n = 0; n < 8; n++) {
        c0[n] = sp[n][0]; c1[n] = sp[n][1];
        sx0[n] = sp[n][2]; sx1[n] = sp[n][3];
        soff[n] = (unsigned)sch[n] * HWx;
    }
    float fa[8] = {0,0,0,0,0,0,0,0};

    const float* pb = pred + (size_t)b * 12 * HWx;
    const unsigned* mbi = g_mbits + (size_t)b * HWx / 4;
    unsigned long long* hb = &g_hist[(size_t)(b * 8) * NBINS];

    for (int g = blk * 256 + threadIdx.x; g < HWx / 4; g += BPB * 256) {
        int hw = g * 4;
        int w = hw & (Wx - 1);
        int h = hw >> 10;
        float ybase = (float)h * (1.0f / 1023.0f);
        float4 p0 = *(const float4*)(pb + hw);
        float4 p1 = *(const float4*)(pb + HWx + hw);
        float e0[4], e1[4];
        e0[0] = tanh_approx(p0.x) + (float)(w + 0) * (2.0f / 2047.0f);
        e0[1] = tanh_approx(p0.y) + (float)(w + 1) * (2.0f / 2047.0f);
        e0[2] = tanh_approx(p0.z) + (float)(w + 2) * (2.0f / 2047.0f);
        e0[3] = tanh_approx(p0.w) + (float)(w + 3) * (2.0f / 2047.0f);
        e1[0] = tanh_approx(p1.x) + ybase;
        e1[1] = tanh_approx(p1.y) + ybase;
        e1[2] = tanh_approx(p1.z) + ybase;
        e1[3] = tanh_approx(p1.w) + ybase;
        unsigned bits = mbi[g];

#pragma unroll
        for (int n = 0; n < 8; n++) {
            uint2 svp = *(const uint2*)(sbase + soff[n] + hw);
            __half2 hA = *reinterpret_cast<__half2*>(&svp.x);
            __half2 hB = *reinterpret_cast<__half2*>(&svp.y);
            float2 fA = __half22float2(hA);
            float2 fB = __half22float2(hB);
            float sv[4] = {fA.x, fA.y, fB.x, fB.y};
#pragma unroll
            for (int j = 0; j < 4; j++) {
                unsigned lab = (bits >> (n + j * 8)) & 1u;
                float mf = (float)lab;
                float dx = e0[j] - c0[n];
                float dy = e1[j] - c1[n];
                float d2 = fmaf(dx * dx, sx0[n], dy * dy * sx1[n]);
                float dist = __expf(-d2);
                float eb = fabsf(dist - mf) * (2.0f * BIN_SCALE);
                int bin = min((int)eb, NBINS - 1);
                atomicAdd(&hb[(size_t)n * NBINS + bin],
                          lab ? (1ull << 32) : 1ull);
                float dd = sv[j] - dist;
                fa[n] = fmaf(mf * dd, dd, fa[n]);
            }
        }
    }

    __shared__ float s_fg[8][8];
    int warp = threadIdx.x >> 5, lane = threadIdx.x & 31;
#pragma unroll
    for (int n = 0; n < 8; n++) {
        float v = wred(fa[n]);
        if (lane == 0) s_fg[n][warp] = v;
    }
    __syncthreads();
    if (threadIdx.x < 8) {
        float s = 0.f;
#pragma unroll
        for (int wv = 0; wv < 8; wv++) s += s_fg[threadIdx.x][wv];
        g_fg_part[(b * 8 + threadIdx.x) * 256 + blk] = s;
    }
}

// ---------------------------------------------------------------- Lovász scan: warp-owned chunks, 2 barriers (launch 4)
__global__ void __launch_bounds__(1024) k_scan() {
    int seg = blockIdx.x;
    int warp = threadIdx.x >> 5, lane = threadIdx.x & 31;
    __shared__ unsigned long long chpre[32];
    __shared__ float rs[32];

    const unsigned long long* hp = &g_hist[(size_t)seg * NBINS];
    float Pf = g_acc[seg * 6 + 0];

    // Phase 1: warp w totals its 1024-bin chunk (descending ranks [w*1024,(w+1)*1024))
    unsigned long long tot = 0ull;
#pragma unroll
    for (int k = 0; k < 32; k++) {
        int bin = NBINS - 1 - (warp * 1024 + k * 32 + lane);
        tot += hp[bin];
    }
#pragma unroll
    for (int o = 16; o >= 1; o >>= 1)
        tot += __shfl_down_sync(0xffffffffu, tot, o);
    if (lane == 0) chpre[warp] = tot;
    __syncthreads();

    // Phase 2: warp 0 exclusive-scans the 32 chunk totals
    if (warp == 0) {
        unsigned long long v = chpre[lane];
        unsigned long long inc = v;
#pragma unroll
        for (int o = 1; o < 32; o <<= 1) {
            unsigned long long t = __shfl_up_sync(0xffffffffu, inc, o);
            if (lane >= o) inc += t;
        }
        chpre[lane] = inc - v;          // exclusive prefix
    }
    __syncthreads();

    // Phase 3: each warp walks its chunk with a private running carry
    unsigned long long carry = chpre[warp];
    unsigned cp = (unsigned)(carry >> 32);
    unsigned cn = (unsigned)(carry & 0xffffffffu);
    float lov = 0.0f;
    for (int k = 0; k < 32; k++) {
        int bin = NBINS - 1 - (warp * 1024 + k * 32 + lane);
        unsigned long long pair = hp[bin];          // low=neg, high=pos
        unsigned long long inc = pair;
#pragma unroll
        for (int o = 1; o < 32; o <<= 1) {
            unsigned long long t = __shfl_up_sync(0xffffffffu, inc, o);
            if (lane >= o) inc += t;
        }
        unsigned np = (unsigned)(pair >> 32);
        unsigned nn = (unsigned)(pair & 0xffffffffu);
        unsigned cp1 = cp + (unsigned)(inc >> 32);
        unsigned cn1 = cn + (unsigned)(inc & 0xffffffffu);
        if (np | nn) {
            unsigned cp0 = cp1 - np;
            unsigned cn0 = cn1 - nn;
            float j1 = 1.0f - __fdividef(Pf - (float)cp1, fmaxf(Pf + (float)cn1, 1.0f));
            float j0 = 1.0f - __fdividef(Pf - (float)cp0, fmaxf(Pf + (float)cn0, 1.0f));
            lov = fmaf(((float)bin + 0.5f) * (1.0f / BIN_SCALE), j1 - j0, lov);
        }
        unsigned long long rowtot = __shfl_sync(0xffffffffu, inc, 31);
        cp += (unsigned)(rowtot >> 32);
        cn += (unsigned)(rowtot & 0xffffffffu);
    }

    float lf = wred(lov);
    if (lane == 0) rs[warp] = lf;
    __syncthreads();
    if (threadIdx.x < 32) {
        float v = wred(rs[threadIdx.x]);
        if (threadIdx.x == 0) g_lov[seg] = v;
    }
}

// ---------------------------------------------------------------- final (launch 5)
__global__ void __launch_bounds__(1024) k_final(const int* __restrict__ cls_ids,
                                                float* __restrict__ out) {
    __shared__ float s_fg[NSEG];
    __shared__ float s_bg[Bx];
    int warp = threadIdx.x >> 5, lane = threadIdx.x & 31;
    if (warp < NSEG) {
        float v = 0.f;
#pragma unroll
        for (int i = 0; i < 8; i++) v += g_fg_part[warp * 256 + lane + i * 32];
        v = wred(v);
        if (lane == 0) s_fg[warp] = v;
    } else if (warp < NSEG + Bx) {
        int b = warp - NSEG;
        float v = 0.f;
#pragma unroll
        for (int i = 0; i < 8; i++) v += g_bg_part[b * 256 + lane + i * 32];
        v = wred(v);
        if (lane == 0) s_bg[b] = v;
    }
    __syncthreads();
    if (threadIdx.x == 0) {
        float total = 0.f;
        for (int b = 0; b < Bx; b++) {
            float obj = 0.f, inst = 0.f, var = 0.f, fg = 0.f;
            for (int n = 0; n < 8; n++) {
                int seg = b * 8 + n;
                float cnt = g_acc[seg * 6 + 0];
                float valid = (cnt >= MINPIX) ? 1.f : 0.f;
                float cs = fmaxf(cnt, 1.f);
                float S0 = g_acc[seg * 6 + 3];
                float S1 = g_acc[seg * 6 + 4];
                float Q  = g_acc[seg * 6 + 5];
                float vi = (Q - (S0 * S0 + S1 * S1) / cs) / (2.f * cs);
                obj += valid;
                inst += g_lov[seg] * valid;
                var += vi * valid;
                fg += FGW[cls_ids[seg]] * s_fg[seg] * valid;
            }
            float os = fmaxf(obj, 1.f);
            float seed_l = (s_bg[b] + fg) * (1.0f / (float)HWx);
            total += inst / os + 10.f * (var / os) + seed_l;
        }
        out[0] = total * 0.5f;
    }
}

// ---------------------------------------------------------------- launch
extern "C" void kernel_launch(void* const* d_in, const int* in_sizes, int n_in,
                              void* d_out, int out_size) {
    const float* pred = (const float*)d_in[0];
    const int* bbox   = (const int*)d_in[1];
    const int* masks  = (const int*)d_in[2];
    const int* cls    = (const int*)d_in[3];
    (void)in_sizes; (void)n_in; (void)out_size;

    k_seed<<<Bx * BPB, 256>>>(pred, bbox);          // 0 (also zeroes hist)
    k_maskaccum<<<Bx * BPB, 256>>>(pred, masks);    // 1
    k_params<<<1, 1024>>>();                        // 2
    k_pass3<<<Bx * BPB, 256>>>(pred, cls);          // 3 <- profiled
    k_scan<<<NSEG, 1024>>>();                       // 4
    k_final<<<1, 1024>>>(cls, (float*)d_out);       // 5
}

// round 14
// speedup vs baseline: 1.0145x; 1.0145x over previous
#include <cuda_runtime.h>
#include <cuda_fp16.h>

#define Bx     2
#define Hx     512
#define Wx     1024
#define HWx    (Hx * Wx)          // 524288
#define NSEG   16
#define NBINS  32768
#define BIN_SCALE 16384.0f
#define MINPIX 128.0f
#define BPB    256                // blocks per batch for big passes

// ---- globals ----
__device__ __align__(16) unsigned long long g_hist[NSEG * NBINS];  // 4MB; low=neg, high=pos
__device__ __align__(16) float g_acc[NSEG * 6];        // cnt, Se0, Se1, Ss0, Ss1, Q
__device__ __align__(16) float g_lov[NSEG];
__device__ __align__(16) float g_params[NSEG * 4];     // c0 c1 sx0 sx1
// per-block partials (fully overwritten each run; no zeroing needed)
__device__ __align__(16) float g_acc_part[96 * 256];   // [q][blk] q=(b*8+n)*6+j
__device__ __align__(16) float g_bg_part[2 * 256];     // [b][blk]
__device__ __align__(16) float g_fg_part[NSEG * 256];  // [seg][blk]
// scratch
__device__ __align__(16) __half g_seeds[Bx * 8 * HWx];       // [b][c][hw]
__device__ __align__(16) unsigned g_mbits[Bx * HWx / 4];     // byte j: bit n = mask n
// tail-block tickets (self-resetting -> deterministic across graph replays)
__device__ int g_ma_count = 0;
__device__ int g_scan_count = 0;

__device__ const float FGW[8] = {10.0f, 10.0f, 10.0f, 40.0f, 80.0f, 100.0f, 60.0f, 20.0f};

__device__ __forceinline__ float wred(float v) {
    v += __shfl_down_sync(0xffffffffu, v, 16);
    v += __shfl_down_sync(0xffffffffu, v, 8);
    v += __shfl_down_sync(0xffffffffu, v, 4);
    v += __shfl_down_sync(0xffffffffu, v, 2);
    v += __shfl_down_sync(0xffffffffu, v, 1);
    return v;
}

__device__ __forceinline__ float tanh_approx(float x) {
    float r;
    asm("tanh.approx.f32 %0, %1;" : "=f"(r) : "f"(x));
    return r;
}
__device__ __forceinline__ __half2 sigmoid2_h(float a, float b) {
    __half2 x = __floats2half2_rn(0.5f * a, 0.5f * b);
    __half2 t;
    asm("tanh.approx.f16x2 %0, %1;" : "=r"(*(unsigned*)&t) : "r"(*(unsigned*)&x));
    const __half2 half2_half = __floats2half2_rn(0.5f, 0.5f);
    return __hfma2(t, half2_half, half2_half);
}

// ---------------------------------------------------------------- k_seed: ch4-11 + bbox, zeroes hist (branch A)
__global__ void __launch_bounds__(256, 4) k_seed(const float* __restrict__ pred,
                                                 const int* __restrict__ bbox) {
    int b = blockIdx.x / BPB;
    int blk = blockIdx.x % BPB;
    const float* pb = pred + (size_t)b * 12 * HWx;
    const int* bbb = bbox + (size_t)b * 9 * HWx;
    __half* sdo = g_seeds + (size_t)b * 8 * HWx;

    // zero the histogram (4MB = 262144 float4s over 512 blocks x 256 threads x 2)
    {
        float4* hz = reinterpret_cast<float4*>(g_hist);
        int base = blockIdx.x * 512 + threadIdx.x;
        hz[base] = make_float4(0.f, 0.f, 0.f, 0.f);
        hz[base + 256] = make_float4(0.f, 0.f, 0.f, 0.f);
    }

    float bg = 0.f;
    for (int g = blk * 256 + threadIdx.x; g < HWx / 4; g += BPB * 256) {
        int hw = g * 4;
#pragma unroll
        for (int c = 0; c < 8; c++) {
            float4 sv = *(const float4*)(pb + (size_t)(4 + c) * HWx + hw);
            int4 bv = *(const int4*)(bbb + (size_t)(1 + c) * HWx + hw);
            __half2 s01 = sigmoid2_h(sv.x, sv.y);
            __half2 s23 = sigmoid2_h(sv.z, sv.w);
            float2 f01 = __half22float2(s01);
            float2 f23 = __half22float2(s23);
            if (bv.x == 0) bg = fmaf(f01.x, f01.x, bg);
            if (bv.y == 0) bg = fmaf(f01.y, f01.y, bg);
            if (bv.z == 0) bg = fmaf(f23.x, f23.x, bg);
            if (bv.w == 0) bg = fmaf(f23.y, f23.y, bg);
            uint2 pk;
            pk.x = *reinterpret_cast<unsigned*>(&s01);
            pk.y = *reinterpret_cast<unsigned*>(&s23);
            *(uint2*)(sdo + (size_t)c * HWx + hw) = pk;
        }
    }
    __shared__ float s_bg[8];
    int warp = threadIdx.x >> 5, lane = threadIdx.x & 31;
    bg = wred(bg);
    if (lane == 0) s_bg[warp] = bg;
    __syncthreads();
    if (threadIdx.x == 0) {
        float s = 0.f;
#pragma unroll
        for (int wv = 0; wv < 8; wv++) s += s_bg[wv];
        g_bg_part[b * 256 + blk] = s;
    }
}

// ---------------------------------------------------------------- k_maskaccum (+fused params tail) (branch B)
__global__ void __launch_bounds__(256) k_maskaccum(const float* __restrict__ pred,
                                                   const int* __restrict__ masks) {
    int b = blockIdx.x / BPB;
    int blk = blockIdx.x % BPB;
    const float* pb = pred + (size_t)b * 12 * HWx;
    const int* mb  = masks + (size_t)b * 8 * HWx;
    unsigned* mbo = g_mbits + (size_t)b * HWx / 4;

    float acc[8][5];   // Se0, Se1, Ss0, Ss1, Q
    int cnt[8];
#pragma unroll
    for (int n = 0; n < 8; n++) {
        cnt[n] = 0;
#pragma unroll
        for (int j = 0; j < 5; j++) acc[n][j] = 0.f;
    }

    for (int g = blk * 256 + threadIdx.x; g < HWx / 4; g += BPB * 256) {
        int hw = g * 4;
        int w = hw & (Wx - 1);
        int h = hw >> 10;
        float ybase = (float)h * (1.0f / 1023.0f);

        unsigned bits = 0;
#pragma unroll
        for (int n = 0; n < 8; n++) {
            int4 mv = *(const int4*)(mb + (size_t)n * HWx + hw);
            if (mv.x > 0) bits |= (1u << (n + 0));
            if (mv.y > 0) bits |= (1u << (n + 8));
            if (mv.z > 0) bits |= (1u << (n + 16));
            if (mv.w > 0) bits |= (1u << (n + 24));
        }
        mbo[g] = bits;

        float4 p0 = *(const float4*)(pb + hw);
        float4 p1 = *(const float4*)(pb + HWx + hw);
        float4 s0v = *(const float4*)(pb + 2 * HWx + hw);
        float4 s1v = *(const float4*)(pb + 3 * HWx + hw);

        float e0[4], e1[4];
        e0[0] = tanh_approx(p0.x) + (float)(w + 0) * (2.0f / 2047.0f);
        e0[1] = tanh_approx(p0.y) + (float)(w + 1) * (2.0f / 2047.0f);
        e0[2] = tanh_approx(p0.z) + (float)(w + 2) * (2.0f / 2047.0f);
        e0[3] = tanh_approx(p0.w) + (float)(w + 3) * (2.0f / 2047.0f);
        e1[0] = tanh_approx(p1.x) + ybase;
        e1[1] = tanh_approx(p1.y) + ybase;
        e1[2] = tanh_approx(p1.z) + ybase;
        e1[3] = tanh_approx(p1.w) + ybase;
        float sg0[4] = {s0v.x, s0v.y, s0v.z, s0v.w};
        float sg1[4] = {s1v.x, s1v.y, s1v.z, s1v.w};
        float q4[4];
#pragma unroll
        for (int j = 0; j < 4; j++) q4[j] = fmaf(sg0[j], sg0[j], sg1[j] * sg1[j]);

#pragma unroll
        for (int n = 0; n < 8; n++) {
            cnt[n] += __popc(bits & (0x01010101u << n));
#pragma unroll
            for (int j = 0; j < 4; j++) {
                if ((bits >> (n + j * 8)) & 1u) {
                    acc[n][0] += e0[j];
                    acc[n][1] += e1[j];
                    acc[n][2] += sg0[j];
                    acc[n][3] += sg1[j];
                    acc[n][4] += q4[j];
                }
            }
        }
    }

    __shared__ float s_red[48][8];
    int warp = threadIdx.x >> 5, lane = threadIdx.x & 31;
#pragma unroll
    for (int n = 0; n < 8; n++) {
        float v;
        v = wred((float)cnt[n]); if (lane == 0) s_red[n * 6 + 0][warp] = v;
#pragma unroll
        for (int j = 0; j < 5; j++) {
            v = wred(acc[n][j]);
            if (lane == 0) s_red[n * 6 + 1 + j][warp] = v;
        }
    }
    __syncthreads();
    if (threadIdx.x < 48) {
        float s = 0.f;
#pragma unroll
        for (int wv = 0; wv < 8; wv++) s += s_red[threadIdx.x][wv];
        int q = (b * 8 + (threadIdx.x / 6)) * 6 + (threadIdx.x % 6);
        g_acc_part[q * 256 + blk] = s;
    }

    // ---- fused params tail: last block reduces partials ----
    __threadfence();
    __shared__ int s_ticket;
    if (threadIdx.x == 0) s_ticket = atomicAdd(&g_ma_count, 1);
    __syncthreads();
    if (s_ticket == Bx * BPB - 1) {
        __threadfence();
        __shared__ float sq[96];
        for (int q = warp; q < 96; q += 8) {
            float v = 0.f;
#pragma unroll
            for (int i = 0; i < 8; i++) v += g_acc_part[q * 256 + lane + i * 32];
            v = wred(v);
            if (lane == 0) sq[q] = v;
        }
        __syncthreads();
        int tid = threadIdx.x;
        if (tid < NSEG) {
            float cntv = sq[tid * 6 + 0];
            float cs = fmaxf(cntv, 1.f);
            float inv = 1.f / cs;
#pragma unroll
            for (int j = 0; j < 6; j++) g_acc[tid * 6 + j] = sq[tid * 6 + j];
            g_params[tid * 4 + 0] = sq[tid * 6 + 1] * inv;
            g_params[tid * 4 + 1] = sq[tid * 6 + 2] * inv;
            g_params[tid * 4 + 2] = expf(sq[tid * 6 + 3] * inv * 10.f);
            g_params[tid * 4 + 3] = expf(sq[tid * 6 + 4] * inv * 10.f);
        }
        if (threadIdx.x == 0) g_ma_count = 0;   // self-reset for graph replay
    }
}

// ---------------------------------------------------------------- pass3: dist, hist, seed_fg
__global__ void __launch_bounds__(256, 2) k_pass3(const float* __restrict__ pred,
                                                  const int* __restrict__ cls_ids) {
    int b = blockIdx.x / BPB;
    int blk = blockIdx.x % BPB;

    __shared__ float sp[8][4];
    __shared__ int sch[8];
    if (threadIdx.x < 32) {
        int n = threadIdx.x / 4, k = threadIdx.x % 4;
        sp[n][k] = g_params[(b * 8 + n) * 4 + k];
    }
    if (threadIdx.x < 8) sch[threadIdx.x] = cls_ids[b * 8 + threadIdx.x];
    __syncthreads();

    float c0[8], c1[8], sx0[8], sx1[8];
    unsigned soff[8];
    const __half* sbase = g_seeds + (size_t)b * 8 * HWx;
#pragma unroll
    for (int n = 0; n < 8; n++) {
        c0[n] = sp[n][0]; c1[n] = sp[n][1];
        sx0[n] = sp[n][2]; sx1[n] = sp[n][3];
        soff[n] = (unsigned)sch[n] * HWx;
    }
    float fa[8] = {0,0,0,0,0,0,0,0};

    const float* pb = pred + (size_t)b * 12 * HWx;
    const unsigned* mbi = g_mbits + (size_t)b * HWx / 4;
    unsigned long long* hb = &g_hist[(size_t)(b * 8) * NBINS];

    for (int g = blk * 256 + threadIdx.x; g < HWx / 4; g += BPB * 256) {
        int hw = g * 4;
        int w = hw & (Wx - 1);
        int h = hw >> 10;
        float ybase = (float)h * (1.0f / 1023.0f);
        float4 p0 = *(const float4*)(pb + hw);
        float4 p1 = *(const float4*)(pb + HWx + hw);
        float e0[4], e1[4];
        e0[0] = tanh_approx(p0.x) + (float)(w + 0) * (2.0f / 2047.0f);
        e0[1] = tanh_approx(p0.y) + (float)(w + 1) * (2.0f / 2047.0f);
        e0[2] = tanh_approx(p0.z) + (float)(w + 2) * (2.0f / 2047.0f);
        e0[3] = tanh_approx(p0.w) + (float)(w + 3) * (2.0f / 2047.0f);
        e1[0] = tanh_approx(p1.x) + ybase;
        e1[1] = tanh_approx(p1.y) + ybase;
        e1[2] = tanh_approx(p1.z) + ybase;
        e1[3] = tanh_approx(p1.w) + ybase;
        unsigned bits = mbi[g];

#pragma unroll
        for (int n = 0; n < 8; n++) {
            uint2 svp = *(const uint2*)(sbase + soff[n] + hw);
            __half2 hA = *reinterpret_cast<__half2*>(&svp.x);
            __half2 hB = *reinterpret_cast<__half2*>(&svp.y);
            float2 fA = __half22float2(hA);
            float2 fB = __half22float2(hB);
            float sv[4] = {fA.x, fA.y, fB.x, fB.y};
#pragma unroll
            for (int j = 0; j < 4; j++) {
                unsigned lab = (bits >> (n + j * 8)) & 1u;
                float mf = (float)lab;
                float dx = e0[j] - c0[n];
                float dy = e1[j] - c1[n];
                float d2 = fmaf(dx * dx, sx0[n], dy * dy * sx1[n]);
                float dist = __expf(-d2);
                float eb = fabsf(dist - mf) * (2.0f * BIN_SCALE);
                int bin = min((int)eb, NBINS - 1);
                atomicAdd(&hb[(size_t)n * NBINS + bin],
                          lab ? (1ull << 32) : 1ull);
                float dd = sv[j] - dist;
                fa[n] = fmaf(mf * dd, dd, fa[n]);
            }
        }
    }

    __shared__ float s_fg[8][8];
    int warp = threadIdx.x >> 5, lane = threadIdx.x & 31;
#pragma unroll
    for (int n = 0; n < 8; n++) {
        float v = wred(fa[n]);
        if (lane == 0) s_fg[n][warp] = v;
    }
    __syncthreads();
    if (threadIdx.x < 8) {
        float s = 0.f;
#pragma unroll
        for (int wv = 0; wv < 8; wv++) s += s_fg[threadIdx.x][wv];
        g_fg_part[(b * 8 + threadIdx.x) * 256 + blk] = s;
    }
}

// ---------------------------------------------------------------- scan (+fused final tail)
__global__ void __launch_bounds__(1024) k_scan(const int* __restrict__ cls_ids,
                                               float* __restrict__ out) {
    int seg = blockIdx.x;
    int warp = threadIdx.x >> 5, lane = threadIdx.x & 31;
    __shared__ unsigned long long chpre[32];
    __shared__ float rs[32];

    const unsigned long long* hp = &g_hist[(size_t)seg * NBINS];
    float Pf = g_acc[seg * 6 + 0];

    // Phase 1: warp w totals its 1024-bin chunk
    unsigned long long tot = 0ull;
#pragma unroll
    for (int k = 0; k < 32; k++) {
        int bin = NBINS - 1 - (warp * 1024 + k * 32 + lane);
        tot += hp[bin];
    }
#pragma unroll
    for (int o = 16; o >= 1; o >>= 1)
        tot += __shfl_down_sync(0xffffffffu, tot, o);
    if (lane == 0) chpre[warp] = tot;
    __syncthreads();

    // Phase 2: warp 0 exclusive-scans the 32 chunk totals
    if (warp == 0) {
        unsigned long long v = chpre[lane];
        unsigned long long inc = v;
#pragma unroll
        for (int o = 1; o < 32; o <<= 1) {
            unsigned long long t = __shfl_up_sync(0xffffffffu, inc, o);
            if (lane >= o) inc += t;
        }
        chpre[lane] = inc - v;
    }
    __syncthreads();

    // Phase 3: each warp walks its chunk with a private running carry
    unsigned long long carry = chpre[warp];
    unsigned cp = (unsigned)(carry >> 32);
    unsigned cn = (unsigned)(carry & 0xffffffffu);
    float lov = 0.0f;
    for (int k = 0; k < 32; k++) {
        int bin = NBINS - 1 - (warp * 1024 + k * 32 + lane);
        unsigned long long pair = hp[bin];
        unsigned long long inc = pair;
#pragma unroll
        for (int o = 1; o < 32; o <<= 1) {
            unsigned long long t = __shfl_up_sync(0xffffffffu, inc, o);
            if (lane >= o) inc += t;
        }
        unsigned np = (unsigned)(pair >> 32);
        unsigned nn = (unsigned)(pair & 0xffffffffu);
        unsigned cp1 = cp + (unsigned)(inc >> 32);
        unsigned cn1 = cn + (unsigned)(inc & 0xffffffffu);
        if (np | nn) {
            unsigned cp0 = cp1 - np;
            unsigned cn0 = cn1 - nn;
            float j1 = 1.0f - __fdividef(Pf - (float)cp1, fmaxf(Pf + (float)cn1, 1.0f));
            float j0 = 1.0f - __fdividef(Pf - (float)cp0, fmaxf(Pf + (float)cn0, 1.0f));
            lov = fmaf(((float)bin + 0.5f) * (1.0f / BIN_SCALE), j1 - j0, lov);
        }
        unsigned long long rowtot = __shfl_sync(0xffffffffu, inc, 31);
        cp += (unsigned)(rowtot >> 32);
        cn += (unsigned)(rowtot & 0xffffffffu);
    }

    float lf = wred(lov);
    if (lane == 0) rs[warp] = lf;
    __syncthreads();
    if (threadIdx.x < 32) {
        float v = wred(rs[threadIdx.x]);
        if (threadIdx.x == 0) g_lov[seg] = v;
    }

    // ---- fused final tail: last scan block combines everything ----
    __threadfence();
    __shared__ int s_ticket;
    if (threadIdx.x == 0) s_ticket = atomicAdd(&g_scan_count, 1);
    __syncthreads();
    if (s_ticket == NSEG - 1) {
        __threadfence();
        __shared__ float s_fg[NSEG];
        __shared__ float s_bg[Bx];
        if (warp < NSEG) {
            float v = 0.f;
#pragma unroll
            for (int i = 0; i < 8; i++) v += g_fg_part[warp * 256 + lane + i * 32];
            v = wred(v);
            if (lane == 0) s_fg[warp] = v;
        } else if (warp < NSEG + Bx) {
            int b = warp - NSEG;
            float v = 0.f;
#pragma unroll
            for (int i = 0; i < 8; i++) v += g_bg_part[b * 256 + lane + i * 32];
            v = wred(v);
            if (lane == 0) s_bg[b] = v;
        }
        __syncthreads();
        if (threadIdx.x == 0) {
            float total = 0.f;
            for (int b = 0; b < Bx; b++) {
                float obj = 0.f, inst = 0.f, var = 0.f, fg = 0.f;
                for (int n = 0; n < 8; n++) {
                    int sg = b * 8 + n;
                    float cntv = g_acc[sg * 6 + 0];
                    float valid = (cntv >= MINPIX) ? 1.f : 0.f;
                    float cs = fmaxf(cntv, 1.f);
                    float S0 = g_acc[sg * 6 + 3];
                    float S1 = g_acc[sg * 6 + 4];
                    float Q  = g_acc[sg * 6 + 5];
                    float vi = (Q - (S0 * S0 + S1 * S1) / cs) / (2.f * cs);
                    obj += valid;
                    inst += g_lov[sg] * valid;
                    var += vi * valid;
                    fg += FGW[cls_ids[sg]] * s_fg[sg] * valid;
                }
                float os = fmaxf(obj, 1.f);
                float seed_l = (s_bg[b] + fg) * (1.0f / (float)HWx);
                total += inst / os + 10.f * (var / os) + seed_l;
            }
            out[0] = total * 0.5f;
            g_scan_count = 0;               // self-reset for graph replay
        }
    }
}

// ---------------------------------------------------------------- launch: fork/join over two streams
extern "C" void kernel_launch(void* const* d_in, const int* in_sizes, int n_in,
                              void* d_out, int out_size) {
    const float* pred = (const float*)d_in[0];
    const int* bbox   = (const int*)d_in[1];
    const int* masks  = (const int*)d_in[2];
    const int* cls    = (const int*)d_in[3];
    (void)in_sizes; (void)n_in; (void)out_size;

    static cudaStream_t s2 = nullptr;
    static cudaEvent_t evFork = nullptr, evJoin = nullptr;
    if (s2 == nullptr) {
        cudaStreamCreateWithFlags(&s2, cudaStreamNonBlocking);
        cudaEventCreateWithFlags(&evFork, cudaEventDisableTiming);
        cudaEventCreateWithFlags(&evJoin, cudaEventDisableTiming);
    }

    // fork: branch B (maskaccum + fused params) on s2, branch A (seed) on capture stream
    cudaEventRecord(evFork, 0);
    cudaStreamWaitEvent(s2, evFork, 0);
    k_maskaccum<<<Bx * BPB, 256, 0, s2>>>(pred, masks);
    k_seed<<<Bx * BPB, 256>>>(pred, bbox);
    // join
    cudaEventRecord(evJoin, s2);
    cudaStreamWaitEvent(0, evJoin, 0);

    k_pass3<<<Bx * BPB, 256>>>(pred, cls);
    k_scan<<<NSEG, 1024>>>(cls, (float*)d_out);
}

// round 16
// speedup vs baseline: 1.0719x; 1.0566x over previous
#include <cuda_runtime.h>
#include <cuda_fp16.h>

#define Bx     2
#define Hx     512
#define Wx     1024
#define HWx    (Hx * Wx)          // 524288
#define NSEG   16
#define NBINS  32768
#define BIN_SCALE 16384.0f
#define MINPIX 128.0f
#define BPB    256                // blocks per batch for big passes
#define SCHUNKS 8                 // scan chunks per segment
#define CHBINS (NBINS / SCHUNKS)  // 4096 bins per scan block

// ---- globals ----
__device__ __align__(16) unsigned long long g_hist[NSEG * NBINS];  // 4MB; low=neg, high=pos
__device__ __align__(16) float g_acc[NSEG * 6];        // cnt, Se0, Se1, Ss0, Ss1, Q
__device__ __align__(16) float g_lov_part[NSEG * SCHUNKS];
__device__ __align__(16) float g_params[NSEG * 4];     // c0 c1 sx0 sx1
// per-block partials (fully overwritten each run; no zeroing needed)
__device__ __align__(16) float g_acc_part[96 * 256];   // [q][blk] q=(b*8+n)*6+j
__device__ __align__(16) float g_bg_part[2 * 256];     // [b][blk]
__device__ __align__(16) float g_fg_part[NSEG * 256];  // [seg][blk]
// scratch
__device__ __align__(16) __half g_seeds[Bx * 8 * HWx];       // [b][c][hw]
__device__ __align__(16) unsigned g_mbits[Bx * HWx / 4];     // byte j: bit n = mask n
// tail-block tickets (self-resetting -> deterministic across graph replays)
__device__ int g_ma_count = 0;
__device__ int g_scan_count = 0;

__device__ const float FGW[8] = {10.0f, 10.0f, 10.0f, 40.0f, 80.0f, 100.0f, 60.0f, 20.0f};

__device__ __forceinline__ float wred(float v) {
    v += __shfl_down_sync(0xffffffffu, v, 16);
    v += __shfl_down_sync(0xffffffffu, v, 8);
    v += __shfl_down_sync(0xffffffffu, v, 4);
    v += __shfl_down_sync(0xffffffffu, v, 2);
    v += __shfl_down_sync(0xffffffffu, v, 1);
    return v;
}
__device__ __forceinline__ unsigned long long wred64(unsigned long long v) {
    v += __shfl_down_sync(0xffffffffu, v, 16);
    v += __shfl_down_sync(0xffffffffu, v, 8);
    v += __shfl_down_sync(0xffffffffu, v, 4);
    v += __shfl_down_sync(0xffffffffu, v, 2);
    v += __shfl_down_sync(0xffffffffu, v, 1);
    return v;
}

__device__ __forceinline__ float tanh_approx(float x) {
    float r;
    asm("tanh.approx.f32 %0, %1;" : "=f"(r) : "f"(x));
    return r;
}
__device__ __forceinline__ __half2 sigmoid2_h(float a, float b) {
    __half2 x = __floats2half2_rn(0.5f * a, 0.5f * b);
    __half2 t;
    asm("tanh.approx.f16x2 %0, %1;" : "=r"(*(unsigned*)&t) : "r"(*(unsigned*)&x));
    const __half2 half2_half = __floats2half2_rn(0.5f, 0.5f);
    return __hfma2(t, half2_half, half2_half);
}

// ---------------------------------------------------------------- k_seed: ch4-11 + bbox, zeroes hist (branch A)
__global__ void __launch_bounds__(256, 4) k_seed(const float* __restrict__ pred,
                                                 const int* __restrict__ bbox) {
    int b = blockIdx.x / BPB;
    int blk = blockIdx.x % BPB;
    const float* pb = pred + (size_t)b * 12 * HWx;
    const int* bbb = bbox + (size_t)b * 9 * HWx;
    __half* sdo = g_seeds + (size_t)b * 8 * HWx;

    // zero the histogram (4MB = 262144 float4s over 512 blocks x 256 threads x 2)
    {
        float4* hz = reinterpret_cast<float4*>(g_hist);
        int base = blockIdx.x * 512 + threadIdx.x;
        hz[base] = make_float4(0.f, 0.f, 0.f, 0.f);
        hz[base + 256] = make_float4(0.f, 0.f, 0.f, 0.f);
    }

    float bg = 0.f;
    for (int g = blk * 256 + threadIdx.x; g < HWx / 4; g += BPB * 256) {
        int hw = g * 4;
#pragma unroll
        for (int c = 0; c < 8; c++) {
            float4 sv = *(const float4*)(pb + (size_t)(4 + c) * HWx + hw);
            int4 bv = *(const int4*)(bbb + (size_t)(1 + c) * HWx + hw);
            __half2 s01 = sigmoid2_h(sv.x, sv.y);
            __half2 s23 = sigmoid2_h(sv.z, sv.w);
            float2 f01 = __half22float2(s01);
            float2 f23 = __half22float2(s23);
            if (bv.x == 0) bg = fmaf(f01.x, f01.x, bg);
            if (bv.y == 0) bg = fmaf(f01.y, f01.y, bg);
            if (bv.z == 0) bg = fmaf(f23.x, f23.x, bg);
            if (bv.w == 0) bg = fmaf(f23.y, f23.y, bg);
            uint2 pk;
            pk.x = *reinterpret_cast<unsigned*>(&s01);
            pk.y = *reinterpret_cast<unsigned*>(&s23);
            *(uint2*)(sdo + (size_t)c * HWx + hw) = pk;
        }
    }
    __shared__ float s_bg[8];
    int warp = threadIdx.x >> 5, lane = threadIdx.x & 31;
    bg = wred(bg);
    if (lane == 0) s_bg[warp] = bg;
    __syncthreads();
    if (threadIdx.x == 0) {
        float s = 0.f;
#pragma unroll
        for (int wv = 0; wv < 8; wv++) s += s_bg[wv];
        g_bg_part[b * 256 + blk] = s;
    }
}

// ---------------------------------------------------------------- k_maskaccum (+fused params tail) (branch B)
__global__ void __launch_bounds__(256) k_maskaccum(const float* __restrict__ pred,
                                                   const int* __restrict__ masks) {
    int b = blockIdx.x / BPB;
    int blk = blockIdx.x % BPB;
    const float* pb = pred + (size_t)b * 12 * HWx;
    const int* mb  = masks + (size_t)b * 8 * HWx;
    unsigned* mbo = g_mbits + (size_t)b * HWx / 4;

    float acc[8][5];   // Se0, Se1, Ss0, Ss1, Q
    int cnt[8];
#pragma unroll
    for (int n = 0; n < 8; n++) {
        cnt[n] = 0;
#pragma unroll
        for (int j = 0; j < 5; j++) acc[n][j] = 0.f;
    }

    for (int g = blk * 256 + threadIdx.x; g < HWx / 4; g += BPB * 256) {
        int hw = g * 4;
        int w = hw & (Wx - 1);
        int h = hw >> 10;
        float ybase = (float)h * (1.0f / 1023.0f);

        unsigned bits = 0;
#pragma unroll
        for (int n = 0; n < 8; n++) {
            int4 mv = *(const int4*)(mb + (size_t)n * HWx + hw);
            if (mv.x > 0) bits |= (1u << (n + 0));
            if (mv.y > 0) bits |= (1u << (n + 8));
            if (mv.z > 0) bits |= (1u << (n + 16));
            if (mv.w > 0) bits |= (1u << (n + 24));
        }
        mbo[g] = bits;

        float4 p0 = *(const float4*)(pb + hw);
        float4 p1 = *(const float4*)(pb + HWx + hw);
        float4 s0v = *(const float4*)(pb + 2 * HWx + hw);
        float4 s1v = *(const float4*)(pb + 3 * HWx + hw);

        float e0[4], e1[4];
        e0[0] = tanh_approx(p0.x) + (float)(w + 0) * (2.0f / 2047.0f);
        e0[1] = tanh_approx(p0.y) + (float)(w + 1) * (2.0f / 2047.0f);
        e0[2] = tanh_approx(p0.z) + (float)(w + 2) * (2.0f / 2047.0f);
        e0[3] = tanh_approx(p0.w) + (float)(w + 3) * (2.0f / 2047.0f);
        e1[0] = tanh_approx(p1.x) + ybase;
        e1[1] = tanh_approx(p1.y) + ybase;
        e1[2] = tanh_approx(p1.z) + ybase;
        e1[3] = tanh_approx(p1.w) + ybase;
        float sg0[4] = {s0v.x, s0v.y, s0v.z, s0v.w};
        float sg1[4] = {s1v.x, s1v.y, s1v.z, s1v.w};
        float q4[4];
#pragma unroll
        for (int j = 0; j < 4; j++) q4[j] = fmaf(sg0[j], sg0[j], sg1[j] * sg1[j]);

#pragma unroll
        for (int n = 0; n < 8; n++) {
            cnt[n] += __popc(bits & (0x01010101u << n));
#pragma unroll
            for (int j = 0; j < 4; j++) {
                if ((bits >> (n + j * 8)) & 1u) {
                    acc[n][0] += e0[j];
                    acc[n][1] += e1[j];
                    acc[n][2] += sg0[j];
                    acc[n][3] += sg1[j];
                    acc[n][4] += q4[j];
                }
            }
        }
    }

    __shared__ float s_red[48][8];
    int warp = threadIdx.x >> 5, lane = threadIdx.x & 31;
#pragma unroll
    for (int n = 0; n < 8; n++) {
        float v;
        v = wred((float)cnt[n]); if (lane == 0) s_red[n * 6 + 0][warp] = v;
#pragma unroll
        for (int j = 0; j < 5; j++) {
            v = wred(acc[n][j]);
            if (lane == 0) s_red[n * 6 + 1 + j][warp] = v;
        }
    }
    __syncthreads();
    if (threadIdx.x < 48) {
        float s = 0.f;
#pragma unroll
        for (int wv = 0; wv < 8; wv++) s += s_red[threadIdx.x][wv];
        int q = (b * 8 + (threadIdx.x / 6)) * 6 + (threadIdx.x % 6);
        g_acc_part[q * 256 + blk] = s;
    }

    // ---- fused params tail: last block reduces partials ----
    __threadfence();
    __shared__ int s_ticket;
    if (threadIdx.x == 0) s_ticket = atomicAdd(&g_ma_count, 1);
    __syncthreads();
    if (s_ticket == Bx * BPB - 1) {
        __threadfence();
        __shared__ float sq[96];
        for (int q = warp; q < 96; q += 8) {
            float v = 0.f;
#pragma unroll
            for (int i = 0; i < 8; i++) v += g_acc_part[q * 256 + lane + i * 32];
            v = wred(v);
            if (lane == 0) sq[q] = v;
        }
        __syncthreads();
        int tid = threadIdx.x;
        if (tid < NSEG) {
            float cntv = sq[tid * 6 + 0];
            float cs = fmaxf(cntv, 1.f);
            float inv = 1.f / cs;
#pragma unroll
            for (int j = 0; j < 6; j++) g_acc[tid * 6 + j] = sq[tid * 6 + j];
            g_params[tid * 4 + 0] = sq[tid * 6 + 1] * inv;
            g_params[tid * 4 + 1] = sq[tid * 6 + 2] * inv;
            g_params[tid * 4 + 2] = expf(sq[tid * 6 + 3] * inv * 10.f);
            g_params[tid * 4 + 3] = expf(sq[tid * 6 + 4] * inv * 10.f);
        }
        if (threadIdx.x == 0) g_ma_count = 0;   // self-reset for graph replay
    }
}

// ---------------------------------------------------------------- pass3: dist, hist, seed_fg
__global__ void __launch_bounds__(256, 2) k_pass3(const float* __restrict__ pred,
                                                  const int* __restrict__ cls_ids) {
    int b = blockIdx.x / BPB;
    int blk = blockIdx.x % BPB;

    __shared__ float sp[8][4];
    __shared__ int sch[8];
    if (threadIdx.x < 32) {
        int n = threadIdx.x / 4, k = threadIdx.x % 4;
        sp[n][k] = g_params[(b * 8 + n) * 4 + k];
    }
    if (threadIdx.x < 8) sch[threadIdx.x] = cls_ids[b * 8 + threadIdx.x];
    __syncthreads();

    float c0[8], c1[8], sx0[8], sx1[8];
    unsigned soff[8];
    const __half* sbase = g_seeds + (size_t)b * 8 * HWx;
#pragma unroll
    for (int n = 0; n < 8; n++) {
        c0[n] = sp[n][0]; c1[n] = sp[n][1];
        sx0[n] = sp[n][2]; sx1[n] = sp[n][3];
        soff[n] = (unsigned)sch[n] * HWx;
    }
    float fa[8] = {0,0,0,0,0,0,0,0};

    const float* pb = pred + (size_t)b * 12 * HWx;
    const unsigned* mbi = g_mbits + (size_t)b * HWx / 4;
    unsigned long long* hb = &g_hist[(size_t)(b * 8) * NBINS];

    for (int g = blk * 256 + threadIdx.x; g < HWx / 4; g += BPB * 256) {
        int hw = g * 4;
        int w = hw & (Wx - 1);
        int h = hw >> 10;
        float ybase = (float)h * (1.0f / 1023.0f);
        float4 p0 = *(const float4*)(pb + hw);
        float4 p1 = *(const float4*)(pb + HWx + hw);
        float e0[4], e1[4];
        e0[0] = tanh_approx(p0.x) + (float)(w + 0) * (2.0f / 2047.0f);
        e0[1] = tanh_approx(p0.y) + (float)(w + 1) * (2.0f / 2047.0f);
        e0[2] = tanh_approx(p0.z) + (float)(w + 2) * (2.0f / 2047.0f);
        e0[3] = tanh_approx(p0.w) + (float)(w + 3) * (2.0f / 2047.0f);
        e1[0] = tanh_approx(p1.x) + ybase;
        e1[1] = tanh_approx(p1.y) + ybase;
        e1[2] = tanh_approx(p1.z) + ybase;
        e1[3] = tanh_approx(p1.w) + ybase;
        unsigned bits = mbi[g];

#pragma unroll
        for (int n = 0; n < 8; n++) {
            uint2 svp = *(const uint2*)(sbase + soff[n] + hw);
            __half2 hA = *reinterpret_cast<__half2*>(&svp.x);
            __half2 hB = *reinterpret_cast<__half2*>(&svp.y);
            float2 fA = __half22float2(hA);
            float2 fB = __half22float2(hB);
            float sv[4] = {fA.x, fA.y, fB.x, fB.y};
#pragma unroll
            for (int j = 0; j < 4; j++) {
                unsigned lab = (bits >> (n + j * 8)) & 1u;
                float mf = (float)lab;
                float dx = e0[j] - c0[n];
                float dy = e1[j] - c1[n];
                float d2 = fmaf(dx * dx, sx0[n], dy * dy * sx1[n]);
                float dist = __expf(-d2);
                float eb = fabsf(dist - mf) * (2.0f * BIN_SCALE);
                int bin = min((int)eb, NBINS - 1);
                atomicAdd(&hb[(size_t)n * NBINS + bin],
                          lab ? (1ull << 32) : 1ull);
                float dd = sv[j] - dist;
                fa[n] = fmaf(mf * dd, dd, fa[n]);
            }
        }
    }

    __shared__ float s_fg[8][8];
    int warp = threadIdx.x >> 5, lane = threadIdx.x & 31;
#pragma unroll
    for (int n = 0; n < 8; n++) {
        float v = wred(fa[n]);
        if (lane == 0) s_fg[n][warp] = v;
    }
    __syncthreads();
    if (threadIdx.x < 8) {
        float s = 0.f;
#pragma unroll
        for (int wv = 0; wv < 8; wv++) s += s_fg[threadIdx.x][wv];
        g_fg_part[(b * 8 + threadIdx.x) * 256 + blk] = s;
    }
}

// ---------------------------------------------------------------- scan: 128 blocks (8 chunks/seg), fused final tail
__global__ void __launch_bounds__(1024) k_scan(const int* __restrict__ cls_ids,
                                               float* __restrict__ out) {
    int seg = blockIdx.x >> 3;
    int chunk = blockIdx.x & 7;
    int r0 = chunk * CHBINS;                 // first rank of this chunk
    int warp = threadIdx.x >> 5, lane = threadIdx.x & 31;
    __shared__ unsigned long long chpre[32];
    __shared__ unsigned long long s_carry;
    __shared__ float rs[32];

    const unsigned long long* hp = &g_hist[(size_t)seg * NBINS];
    float Pf = g_acc[seg * 6 + 0];

    // Phase 0: carry-in = sum over ranks [0, r0)  (bins (NBINS-1-r))
    unsigned long long cin = 0ull;
    for (int r = threadIdx.x; r < r0; r += 1024)
        cin += hp[NBINS - 1 - r];
    cin = wred64(cin);
    if (lane == 0) chpre[warp] = cin;
    __syncthreads();
    if (warp == 0) {
        unsigned long long v = chpre[lane];
        v = wred64(v);
        if (lane == 0) s_carry = v;
    }
    __syncthreads();
    unsigned long long carry_in = s_carry;
    __syncthreads();

    // Phase 1: warp w totals its 128-rank slice [r0 + w*128, r0 + (w+1)*128)
    unsigned long long tot = 0ull;
#pragma unroll
    for (int k = 0; k < 4; k++)
        tot += hp[NBINS - 1 - (r0 + warp * 128 + k * 32 + lane)];
    tot = wred64(tot);
    if (lane == 0) chpre[warp] = tot;
    __syncthreads();

    // Phase 2: warp 0 exclusive-scans the 32 slice totals
    if (warp == 0) {
        unsigned long long v = chpre[lane];
        unsigned long long inc = v;
#pragma unroll
        for (int o = 1; o < 32; o <<= 1) {
            unsigned long long t = __shfl_up_sync(0xffffffffu, inc, o);
            if (lane >= o) inc += t;
        }
        chpre[lane] = inc - v;
    }
    __syncthreads();

    // Phase 3: each warp walks its 4 rows with a private running carry
    unsigned long long carry = carry_in + chpre[warp];
    unsigned cp = (unsigned)(carry >> 32);
    unsigned cn = (unsigned)(carry & 0xffffffffu);
    float lov = 0.0f;
#pragma unroll
    for (int k = 0; k < 4; k++) {
        int bin = NBINS - 1 - (r0 + warp * 128 + k * 32 + lane);
        unsigned long long pair = hp[bin];           // low=neg, high=pos
        unsigned long long inc = pair;
#pragma unroll
        for (int o = 1; o < 32; o <<= 1) {
            unsigned long long t = __shfl_up_sync(0xffffffffu, inc, o);
            if (lane >= o) inc += t;
        }
        unsigned np = (unsigned)(pair >> 32);
        unsigned nn = (unsigned)(pair & 0xffffffffu);
        unsigned cp1 = cp + (unsigned)(inc >> 32);
        unsigned cn1 = cn + (unsigned)(inc & 0xffffffffu);
        if (np | nn) {
            unsigned cp0 = cp1 - np;
            unsigned cn0 = cn1 - nn;
            float j1 = 1.0f - __fdividef(Pf - (float)cp1, fmaxf(Pf + (float)cn1, 1.0f));
            float j0 = 1.0f - __fdividef(Pf - (float)cp0, fmaxf(Pf + (float)cn0, 1.0f));
            lov = fmaf(((float)bin + 0.5f) * (1.0f / BIN_SCALE), j1 - j0, lov);
        }
        unsigned long long rowtot = __shfl_sync(0xffffffffu, inc, 31);
        cp += (unsigned)(rowtot >> 32);
        cn += (unsigned)(rowtot & 0xffffffffu);
    }

    float lf = wred(lov);
    if (lane == 0) rs[warp] = lf;
    __syncthreads();
    if (threadIdx.x < 32) {
        float v = wred(rs[threadIdx.x]);
        if (threadIdx.x == 0) g_lov_part[seg * SCHUNKS + chunk] = v;
    }

    // ---- fused final tail: last scan block combines everything ----
    __threadfence();
    __shared__ int s_ticket;
    if (threadIdx.x == 0) s_ticket = atomicAdd(&g_scan_count, 1);
    __syncthreads();
    if (s_ticket == NSEG * SCHUNKS - 1) {
        __threadfence();
        __shared__ float s_fg[NSEG];
        __shared__ float s_bg[Bx];
        if (warp < NSEG) {
            float v = 0.f;
#pragma unroll
            for (int i = 0; i < 8; i++) v += g_fg_part[warp * 256 + lane + i * 32];
            v = wred(v);
            if (lane == 0) s_fg[warp] = v;
        } else if (warp < NSEG + Bx) {
            int b = warp - NSEG;
            float v = 0.f;
#pragma unroll
            for (int i = 0; i < 8; i++) v += g_bg_part[b * 256 + lane + i * 32];
            v = wred(v);
            if (lane == 0) s_bg[b] = v;
        }
        __syncthreads();
        if (threadIdx.x == 0) {
            float total = 0.f;
            for (int b = 0; b < Bx; b++) {
                float obj = 0.f, inst = 0.f, var = 0.f, fg = 0.f;
                for (int n = 0; n < 8; n++) {
                    int sg = b * 8 + n;
                    float cntv = g_acc[sg * 6 + 0];
                    float valid = (cntv >= MINPIX) ? 1.f : 0.f;
                    float cs = fmaxf(cntv, 1.f);
                    float S0 = g_acc[sg * 6 + 3];
                    float S1 = g_acc[sg * 6 + 4];
                    float Q  = g_acc[sg * 6 + 5];
                    float vi = (Q - (S0 * S0 + S1 * S1) / cs) / (2.f * cs);
                    float lv = 0.f;
#pragma unroll
                    for (int c = 0; c < SCHUNKS; c++) lv += g_lov_part[sg * SCHUNKS + c];
                    obj += valid;
                    inst += lv * valid;
                    var += vi * valid;
                    fg += FGW[cls_ids[sg]] * s_fg[sg] * valid;
                }
                float os = fmaxf(obj, 1.f);
                float seed_l = (s_bg[b] + fg) * (1.0f / (float)HWx);
                total += inst / os + 10.f * (var / os) + seed_l;
            }
            out[0] = total * 0.5f;
            g_scan_count = 0;               // self-reset for graph replay
        }
    }
}

// ---------------------------------------------------------------- launch: fork/join over two streams
extern "C" void kernel_launch(void* const* d_in, const int* in_sizes, int n_in,
                              void* d_out, int out_size) {
    const float* pred = (const float*)d_in[0];
    const int* bbox   = (const int*)d_in[1];
    const int* masks  = (const int*)d_in[2];
    const int* cls    = (const int*)d_in[3];
    (void)in_sizes; (void)n_in; (void)out_size;

    static cudaStream_t s2 = nullptr;
    static cudaEvent_t evFork = nullptr, evJoin = nullptr;
    if (s2 == nullptr) {
        cudaStreamCreateWithFlags(&s2, cudaStreamNonBlocking);
        cudaEventCreateWithFlags(&evFork, cudaEventDisableTiming);
        cudaEventCreateWithFlags(&evJoin, cudaEventDisableTiming);
    }

    // fork: branch B (maskaccum + fused params) on s2, branch A (seed+hist zero) on capture stream
    cudaEventRecord(evFork, 0);
    cudaStreamWaitEvent(s2, evFork, 0);
    k_maskaccum<<<Bx * BPB, 256, 0, s2>>>(pred, masks);
    k_seed<<<Bx * BPB, 256>>>(pred, bbox);
    // join
    cudaEventRecord(evJoin, s2);
    cudaStreamWaitEvent(0, evJoin, 0);

    k_pass3<<<Bx * BPB, 256>>>(pred, cls);
    k_scan<<<NSEG * SCHUNKS, 1024>>>(cls, (float*)d_out);
}

// round 17
// speedup vs baseline: 1.0843x; 1.0116x over previous
#include <cuda_runtime.h>
#include <cuda_fp16.h>

#define Bx     2
#define Hx     512
#define Wx     1024
#define HWx    (Hx * Wx)          // 524288
#define NSEG   16
#define NBINS  32768
#define BIN_SCALE 16384.0f
#define MINPIX 128.0f
#define BPB    256                // blocks per batch for big passes
#define SCHUNKS 8                 // scan chunks per segment
#define CHBINS (NBINS / SCHUNKS)  // 4096 bins per scan block

// ---- globals ----
__device__ __align__(16) unsigned long long g_hist[NSEG * NBINS];  // 4MB; low=neg, high=pos
__device__ __align__(16) unsigned long long g_chunk_tot[NSEG * SCHUNKS];
__device__ __align__(16) float g_acc[NSEG * 6];        // cnt, Se0, Se1, Ss0, Ss1, Q
__device__ __align__(16) float g_lov_part[NSEG * SCHUNKS];
__device__ __align__(16) float g_params[NSEG * 4];     // c0 c1 sx0 sx1
// per-block partials (fully overwritten each run; no zeroing needed)
__device__ __align__(16) float g_acc_part[96 * 256];   // [q][blk] q=(b*8+n)*6+j
__device__ __align__(16) float g_bg_part[2 * 256];     // [b][blk]
__device__ __align__(16) float g_fg_part[NSEG * 256];  // [seg][blk]
// scratch
__device__ __align__(16) unsigned g_mbits[Bx * HWx / 4];     // byte j: bit n = mask n
// tail-block tickets (self-resetting -> deterministic across graph replays)
__device__ int g_ma_count = 0;
__device__ int g_scan_count = 0;

__device__ const float FGW[8] = {10.0f, 10.0f, 10.0f, 40.0f, 80.0f, 100.0f, 60.0f, 20.0f};

__device__ __forceinline__ float wred(float v) {
    v += __shfl_down_sync(0xffffffffu, v, 16);
    v += __shfl_down_sync(0xffffffffu, v, 8);
    v += __shfl_down_sync(0xffffffffu, v, 4);
    v += __shfl_down_sync(0xffffffffu, v, 2);
    v += __shfl_down_sync(0xffffffffu, v, 1);
    return v;
}
__device__ __forceinline__ unsigned long long wred64(unsigned long long v) {
    v += __shfl_down_sync(0xffffffffu, v, 16);
    v += __shfl_down_sync(0xffffffffu, v, 8);
    v += __shfl_down_sync(0xffffffffu, v, 4);
    v += __shfl_down_sync(0xffffffffu, v, 2);
    v += __shfl_down_sync(0xffffffffu, v, 1);
    return v;
}

__device__ __forceinline__ float tanh_approx(float x) {
    float r;
    asm("tanh.approx.f32 %0, %1;" : "=f"(r) : "f"(x));
    return r;
}
__device__ __forceinline__ __half2 sigmoid2_h(float a, float b) {
    __half2 x = __floats2half2_rn(0.5f * a, 0.5f * b);
    __half2 t;
    asm("tanh.approx.f16x2 %0, %1;" : "=r"(*(unsigned*)&t) : "r"(*(unsigned*)&x));
    const __half2 half2_half = __floats2half2_rn(0.5f, 0.5f);
    return __hfma2(t, half2_half, half2_half);
}

// ---------------------------------------------------------------- k_seed: bg from ch4-11 + bbox, zeroes hist (branch A)
__global__ void __launch_bounds__(256, 4) k_seed(const float* __restrict__ pred,
                                                 const int* __restrict__ bbox) {
    int b = blockIdx.x / BPB;
    int blk = blockIdx.x % BPB;
    const float* pb = pred + (size_t)b * 12 * HWx;
    const int* bbb = bbox + (size_t)b * 9 * HWx;

    // zero the histogram (4MB = 262144 float4s over 512 blocks x 256 threads x 2)
    {
        float4* hz = reinterpret_cast<float4*>(g_hist);
        int base = blockIdx.x * 512 + threadIdx.x;
        hz[base] = make_float4(0.f, 0.f, 0.f, 0.f);
        hz[base + 256] = make_float4(0.f, 0.f, 0.f, 0.f);
    }

    float bg = 0.f;
    for (int g = blk * 256 + threadIdx.x; g < HWx / 4; g += BPB * 256) {
        int hw = g * 4;
#pragma unroll
        for (int c = 0; c < 8; c++) {
            float4 sv = *(const float4*)(pb + (size_t)(4 + c) * HWx + hw);
            int4 bv = *(const int4*)(bbb + (size_t)(1 + c) * HWx + hw);
            __half2 s01 = sigmoid2_h(sv.x, sv.y);
            __half2 s23 = sigmoid2_h(sv.z, sv.w);
            float2 f01 = __half22float2(s01);
            float2 f23 = __half22float2(s23);
            if (bv.x == 0) bg = fmaf(f01.x, f01.x, bg);
            if (bv.y == 0) bg = fmaf(f01.y, f01.y, bg);
            if (bv.z == 0) bg = fmaf(f23.x, f23.x, bg);
            if (bv.w == 0) bg = fmaf(f23.y, f23.y, bg);
        }
    }
    __shared__ float s_bg[8];
    int warp = threadIdx.x >> 5, lane = threadIdx.x & 31;
    bg = wred(bg);
    if (lane == 0) s_bg[warp] = bg;
    __syncthreads();
    if (threadIdx.x == 0) {
        float s = 0.f;
#pragma unroll
        for (int wv = 0; wv < 8; wv++) s += s_bg[wv];
        g_bg_part[b * 256 + blk] = s;
    }
}

// ---------------------------------------------------------------- k_maskaccum (+fused params tail) (branch B)
__global__ void __launch_bounds__(256) k_maskaccum(const float* __restrict__ pred,
                                                   const int* __restrict__ masks) {
    int b = blockIdx.x / BPB;
    int blk = blockIdx.x % BPB;
    const float* pb = pred + (size_t)b * 12 * HWx;
    const int* mb  = masks + (size_t)b * 8 * HWx;
    unsigned* mbo = g_mbits + (size_t)b * HWx / 4;

    float acc[8][5];   // Se0, Se1, Ss0, Ss1, Q
    int cnt[8];
#pragma unroll
    for (int n = 0; n < 8; n++) {
        cnt[n] = 0;
#pragma unroll
        for (int j = 0; j < 5; j++) acc[n][j] = 0.f;
    }

    for (int g = blk * 256 + threadIdx.x; g < HWx / 4; g += BPB * 256) {
        int hw = g * 4;
        int w = hw & (Wx - 1);
        int h = hw >> 10;
        float ybase = (float)h * (1.0f / 1023.0f);

        unsigned bits = 0;
#pragma unroll
        for (int n = 0; n < 8; n++) {
            int4 mv = *(const int4*)(mb + (size_t)n * HWx + hw);
            if (mv.x > 0) bits |= (1u << (n + 0));
            if (mv.y > 0) bits |= (1u << (n + 8));
            if (mv.z > 0) bits |= (1u << (n + 16));
            if (mv.w > 0) bits |= (1u << (n + 24));
        }
        mbo[g] = bits;

        float4 p0 = *(const float4*)(pb + hw);
        float4 p1 = *(const float4*)(pb + HWx + hw);
        float4 s0v = *(const float4*)(pb + 2 * HWx + hw);
        float4 s1v = *(const float4*)(pb + 3 * HWx + hw);

        float e0[4], e1[4];
        e0[0] = tanh_approx(p0.x) + (float)(w + 0) * (2.0f / 2047.0f);
        e0[1] = tanh_approx(p0.y) + (float)(w + 1) * (2.0f / 2047.0f);
        e0[2] = tanh_approx(p0.z) + (float)(w + 2) * (2.0f / 2047.0f);
        e0[3] = tanh_approx(p0.w) + (float)(w + 3) * (2.0f / 2047.0f);
        e1[0] = tanh_approx(p1.x) + ybase;
        e1[1] = tanh_approx(p1.y) + ybase;
        e1[2] = tanh_approx(p1.z) + ybase;
        e1[3] = tanh_approx(p1.w) + ybase;
        float sg0[4] = {s0v.x, s0v.y, s0v.z, s0v.w};
        float sg1[4] = {s1v.x, s1v.y, s1v.z, s1v.w};
        float q4[4];
#pragma unroll
        for (int j = 0; j < 4; j++) q4[j] = fmaf(sg0[j], sg0[j], sg1[j] * sg1[j]);

#pragma unroll
        for (int n = 0; n < 8; n++) {
            cnt[n] += __popc(bits & (0x01010101u << n));
#pragma unroll
            for (int j = 0; j < 4; j++) {
                if ((bits >> (n + j * 8)) & 1u) {
                    acc[n][0] += e0[j];
                    acc[n][1] += e1[j];
                    acc[n][2] += sg0[j];
                    acc[n][3] += sg1[j];
                    acc[n][4] += q4[j];
                }
            }
        }
    }

    __shared__ float s_red[48][8];
    int warp = threadIdx.x >> 5, lane = threadIdx.x & 31;
#pragma unroll
    for (int n = 0; n < 8; n++) {
        float v;
        v = wred((float)cnt[n]); if (lane == 0) s_red[n * 6 + 0][warp] = v;
#pragma unroll
        for (int j = 0; j < 5; j++) {
            v = wred(acc[n][j]);
            if (lane == 0) s_red[n * 6 + 1 + j][warp] = v;
        }
    }
    __syncthreads();
    if (threadIdx.x < 48) {
        float s = 0.f;
#pragma unroll
        for (int wv = 0; wv < 8; wv++) s += s_red[threadIdx.x][wv];
        int q = (b * 8 + (threadIdx.x / 6)) * 6 + (threadIdx.x % 6);
        g_acc_part[q * 256 + blk] = s;
    }

    // ---- fused params tail: last block reduces partials ----
    __threadfence();
    __shared__ int s_ticket;
    if (threadIdx.x == 0) s_ticket = atomicAdd(&g_ma_count, 1);
    __syncthreads();
    if (s_ticket == Bx * BPB - 1) {
        __threadfence();
        __shared__ float sq[96];
        for (int q = warp; q < 96; q += 8) {
            float v = 0.f;
#pragma unroll
            for (int i = 0; i < 8; i++) v += g_acc_part[q * 256 + lane + i * 32];
            v = wred(v);
            if (lane == 0) sq[q] = v;
        }
        __syncthreads();
        int tid = threadIdx.x;
        if (tid < NSEG) {
            float cntv = sq[tid * 6 + 0];
            float cs = fmaxf(cntv, 1.f);
            float inv = 1.f / cs;
#pragma unroll
            for (int j = 0; j < 6; j++) g_acc[tid * 6 + j] = sq[tid * 6 + j];
            g_params[tid * 4 + 0] = sq[tid * 6 + 1] * inv;
            g_params[tid * 4 + 1] = sq[tid * 6 + 2] * inv;
            g_params[tid * 4 + 2] = expf(sq[tid * 6 + 3] * inv * 10.f);
            g_params[tid * 4 + 3] = expf(sq[tid * 6 + 4] * inv * 10.f);
        }
        if (threadIdx.x == 0) g_ma_count = 0;   // self-reset for graph replay
    }
}

// ---------------------------------------------------------------- pass3: dist, hist, seed_fg (sigmoid recomputed)
__global__ void __launch_bounds__(256, 2) k_pass3(const float* __restrict__ pred,
                                                  const int* __restrict__ cls_ids) {
    int b = blockIdx.x / BPB;
    int blk = blockIdx.x % BPB;

    __shared__ float sp[8][4];
    __shared__ int sch[8];
    if (threadIdx.x < 32) {
        int n = threadIdx.x / 4, k = threadIdx.x % 4;
        sp[n][k] = g_params[(b * 8 + n) * 4 + k];
    }
    if (threadIdx.x < 8) sch[threadIdx.x] = cls_ids[b * 8 + threadIdx.x];
    __syncthreads();

    float c0[8], c1[8], sx0[8], sx1[8];
    unsigned soff[8];                       // pred element offsets for seed channels
    const float* pb = pred + (size_t)b * 12 * HWx;
#pragma unroll
    for (int n = 0; n < 8; n++) {
        c0[n] = sp[n][0]; c1[n] = sp[n][1];
        sx0[n] = sp[n][2]; sx1[n] = sp[n][3];
        soff[n] = (unsigned)(4 + sch[n]) * HWx;
    }
    float fa[8] = {0,0,0,0,0,0,0,0};

    const unsigned* mbi = g_mbits + (size_t)b * HWx / 4;
    unsigned long long* hb = &g_hist[(size_t)(b * 8) * NBINS];

    for (int g = blk * 256 + threadIdx.x; g < HWx / 4; g += BPB * 256) {
        int hw = g * 4;
        int w = hw & (Wx - 1);
        int h = hw >> 10;
        float ybase = (float)h * (1.0f / 1023.0f);
        float4 p0 = *(const float4*)(pb + hw);
        float4 p1 = *(const float4*)(pb + HWx + hw);
        float e0[4], e1[4];
        e0[0] = tanh_approx(p0.x) + (float)(w + 0) * (2.0f / 2047.0f);
        e0[1] = tanh_approx(p0.y) + (float)(w + 1) * (2.0f / 2047.0f);
        e0[2] = tanh_approx(p0.z) + (float)(w + 2) * (2.0f / 2047.0f);
        e0[3] = tanh_approx(p0.w) + (float)(w + 3) * (2.0f / 2047.0f);
        e1[0] = tanh_approx(p1.x) + ybase;
        e1[1] = tanh_approx(p1.y) + ybase;
        e1[2] = tanh_approx(p1.z) + ybase;
        e1[3] = tanh_approx(p1.w) + ybase;
        unsigned bits = mbi[g];

#pragma unroll
        for (int n = 0; n < 8; n++) {
            float4 sraw = *(const float4*)(pb + soff[n] + hw);
            __half2 s01 = sigmoid2_h(sraw.x, sraw.y);
            __half2 s23 = sigmoid2_h(sraw.z, sraw.w);
            float2 fA = __half22float2(s01);
            float2 fB = __half22float2(s23);
            float sv[4] = {fA.x, fA.y, fB.x, fB.y};
#pragma unroll
            for (int j = 0; j < 4; j++) {
                unsigned lab = (bits >> (n + j * 8)) & 1u;
                float mf = (float)lab;
                float dx = e0[j] - c0[n];
                float dy = e1[j] - c1[n];
                float d2 = fmaf(dx * dx, sx0[n], dy * dy * sx1[n]);
                float dist = __expf(-d2);
                float eb = fabsf(dist - mf) * (2.0f * BIN_SCALE);
                int bin = min((int)eb, NBINS - 1);
                atomicAdd(&hb[(size_t)n * NBINS + bin],
                          lab ? (1ull << 32) : 1ull);
                float dd = sv[j] - dist;
                fa[n] = fmaf(mf * dd, dd, fa[n]);
            }
        }
    }

    __shared__ float s_fg[8][8];
    int warp = threadIdx.x >> 5, lane = threadIdx.x & 31;
#pragma unroll
    for (int n = 0; n < 8; n++) {
        float v = wred(fa[n]);
        if (lane == 0) s_fg[n][warp] = v;
    }
    __syncthreads();
    if (threadIdx.x < 8) {
        float s = 0.f;
#pragma unroll
        for (int wv = 0; wv < 8; wv++) s += s_fg[threadIdx.x][wv];
        g_fg_part[(b * 8 + threadIdx.x) * 256 + blk] = s;
    }
}

// ---------------------------------------------------------------- chunk totals (128 blocks)
__global__ void __launch_bounds__(1024) k_chunksum() {
    int seg = blockIdx.x >> 3;
    int chunk = blockIdx.x & 7;
    const unsigned long long* hp = &g_hist[(size_t)seg * NBINS + (size_t)(7 - chunk) * CHBINS];
    // chunk c covers RANKS [c*CHBINS,(c+1)*CHBINS) = BINS [NBINS-(c+1)*CHBINS, NBINS-c*CHBINS)
    unsigned long long tot = 0ull;
#pragma unroll
    for (int k = 0; k < 4; k++)
        tot += hp[k * 1024 + threadIdx.x];
    int warp = threadIdx.x >> 5, lane = threadIdx.x & 31;
    __shared__ unsigned long long sred[32];
    tot = wred64(tot);
    if (lane == 0) sred[warp] = tot;
    __syncthreads();
    if (warp == 0) {
        unsigned long long v = sred[lane];
        v = wred64(v);
        if (lane == 0) g_chunk_tot[seg * SCHUNKS + chunk] = v;
    }
}

// ---------------------------------------------------------------- scan: 128 blocks (8 chunks/seg), fused final tail
__global__ void __launch_bounds__(1024) k_scan(const int* __restrict__ cls_ids,
                                               float* __restrict__ out) {
    int seg = blockIdx.x >> 3;
    int chunk = blockIdx.x & 7;
    int r0 = chunk * CHBINS;                 // first rank of this chunk
    int warp = threadIdx.x >> 5, lane = threadIdx.x & 31;
    __shared__ unsigned long long chpre[32];
    __shared__ unsigned long long s_carry;
    __shared__ float rs[32];

    const unsigned long long* hp = &g_hist[(size_t)seg * NBINS];
    float Pf = g_acc[seg * 6 + 0];

    // Phase 0: carry-in = sum of totals of lower-ranked chunks (precomputed)
    if (threadIdx.x < 32) {
        unsigned long long v = (lane < chunk) ? g_chunk_tot[seg * SCHUNKS + lane] : 0ull;
        v = wred64(v);
        if (lane == 0) s_carry = v;
    }
    __syncthreads();
    unsigned long long carry_in = s_carry;

    // Phase 1: warp w totals its 128-rank slice [r0 + w*128, r0 + (w+1)*128)
    unsigned long long tot = 0ull;
#pragma unroll
    for (int k = 0; k < 4; k++)
        tot += hp[NBINS - 1 - (r0 + warp * 128 + k * 32 + lane)];
    tot = wred64(tot);
    if (lane == 0) chpre[warp] = tot;
    __syncthreads();

    // Phase 2: warp 0 exclusive-scans the 32 slice totals
    if (warp == 0) {
        unsigned long long v = chpre[lane];
        unsigned long long inc = v;
#pragma unroll
        for (int o = 1; o < 32; o <<= 1) {
            unsigned long long t = __shfl_up_sync(0xffffffffu, inc, o);
            if (lane >= o) inc += t;
        }
        chpre[lane] = inc - v;
    }
    __syncthreads();

    // Phase 3: each warp walks its 4 rows with a private running carry
    unsigned long long carry = carry_in + chpre[warp];
    unsigned cp = (unsigned)(carry >> 32);
    unsigned cn = (unsigned)(carry & 0xffffffffu);
    float lov = 0.0f;
#pragma unroll
    for (int k = 0; k < 4; k++) {
        int bin = NBINS - 1 - (r0 + warp * 128 + k * 32 + lane);
        unsigned long long pair = hp[bin];           // low=neg, high=pos
        unsigned long long inc = pair;
#pragma unroll
        for (int o = 1; o < 32; o <<= 1) {
            unsigned long long t = __shfl_up_sync(0xffffffffu, inc, o);
            if (lane >= o) inc += t;
        }
        unsigned np = (unsigned)(pair >> 32);
        unsigned nn = (unsigned)(pair & 0xffffffffu);
        unsigned cp1 = cp + (unsigned)(inc >> 32);
        unsigned cn1 = cn + (unsigned)(inc & 0xffffffffu);
        if (np | nn) {
            unsigned cp0 = cp1 - np;
            unsigned cn0 = cn1 - nn;
            float j1 = 1.0f - __fdividef(Pf - (float)cp1, fmaxf(Pf + (float)cn1, 1.0f));
            float j0 = 1.0f - __fdividef(Pf - (float)cp0, fmaxf(Pf + (float)cn0, 1.0f));
            lov = fmaf(((float)bin + 0.5f) * (1.0f / BIN_SCALE), j1 - j0, lov);
        }
        unsigned long long rowtot = __shfl_sync(0xffffffffu, inc, 31);
        cp += (unsigned)(rowtot >> 32);
        cn += (unsigned)(rowtot & 0xffffffffu);
    }

    float lf = wred(lov);
    if (lane == 0) rs[warp] = lf;
    __syncthreads();
    if (threadIdx.x < 32) {
        float v = wred(rs[threadIdx.x]);
        if (threadIdx.x == 0) g_lov_part[seg * SCHUNKS + chunk] = v;
    }

    // ---- fused final tail: last scan block combines everything ----
    __threadfence();
    __shared__ int s_ticket;
    if (threadIdx.x == 0) s_ticket = atomicAdd(&g_scan_count, 1);
    __syncthreads();
    if (s_ticket == NSEG * SCHUNKS - 1) {
        __threadfence();
        __shared__ float s_fg[NSEG];
        __shared__ float s_bg[Bx];
        if (warp < NSEG) {
            float v = 0.f;
#pragma unroll
            for (int i = 0; i < 8; i++) v += g_fg_part[warp * 256 + lane + i * 32];
            v = wred(v);
            if (lane == 0) s_fg[warp] = v;
        } else if (warp < NSEG + Bx) {
            int b = warp - NSEG;
            float v = 0.f;
#pragma unroll
            for (int i = 0; i < 8; i++) v += g_bg_part[b * 256 + lane + i * 32];
            v = wred(v);
            if (lane == 0) s_bg[b] = v;
        }
        __syncthreads();
        if (threadIdx.x == 0) {
            float total = 0.f;
            for (int b = 0; b < Bx; b++) {
                float obj = 0.f, inst = 0.f, var = 0.f, fg = 0.f;
                for (int n = 0; n < 8; n++) {
                    int sg = b * 8 + n;
                    float cntv = g_acc[sg * 6 + 0];
                    float valid = (cntv >= MINPIX) ? 1.f : 0.f;
                    float cs = fmaxf(cntv, 1.f);
                    float S0 = g_acc[sg * 6 + 3];
                    float S1 = g_acc[sg * 6 + 4];
                    float Q  = g_acc[sg * 6 + 5];
                    float vi = (Q - (S0 * S0 + S1 * S1) / cs) / (2.f * cs);
                    float lv = 0.f;
#pragma unroll
                    for (int c = 0; c < SCHUNKS; c++) lv += g_lov_part[sg * SCHUNKS + c];
                    obj += valid;
                    inst += lv * valid;
                    var += vi * valid;
                    fg += FGW[cls_ids[sg]] * s_fg[sg] * valid;
                }
                float os = fmaxf(obj, 1.f);
                float seed_l = (s_bg[b] + fg) * (1.0f / (float)HWx);
                total += inst / os + 10.f * (var / os) + seed_l;
            }
            out[0] = total * 0.5f;
            g_scan_count = 0;               // self-reset for graph replay
        }
    }
}

// ---------------------------------------------------------------- launch: fork/join over two streams
extern "C" void kernel_launch(void* const* d_in, const int* in_sizes, int n_in,
                              void* d_out, int out_size) {
    const float* pred = (const float*)d_in[0];
    const int* bbox   = (const int*)d_in[1];
    const int* masks  = (const int*)d_in[2];
    const int* cls    = (const int*)d_in[3];
    (void)in_sizes; (void)n_in; (void)out_size;

    static cudaStream_t s2 = nullptr;
    static cudaEvent_t evFork = nullptr, evJoin = nullptr;
    if (s2 == nullptr) {
        cudaStreamCreateWithFlags(&s2, cudaStreamNonBlocking);
        cudaEventCreateWithFlags(&evFork, cudaEventDisableTiming);
        cudaEventCreateWithFlags(&evJoin, cudaEventDisableTiming);
    }

    // fork: branch B (maskaccum + fused params) on s2, branch A (seed+hist zero) on capture stream
    cudaEventRecord(evFork, 0);
    cudaStreamWaitEvent(s2, evFork, 0);
    k_maskaccum<<<Bx * BPB, 256, 0, s2>>>(pred, masks);
    k_seed<<<Bx * BPB, 256>>>(pred, bbox);
    // join
    cudaEventRecord(evJoin, s2);
    cudaStreamWaitEvent(0, evJoin, 0);

    k_pass3<<<Bx * BPB, 256>>>(pred, cls);
    k_chunksum<<<NSEG * SCHUNKS, 1024>>>();
    k_scan<<<NSEG * SCHUNKS, 1024>>>(cls, (float*)d_out);
}